// round 2
// baseline (speedup 1.0000x reference)
#include <cuda_runtime.h>
#include <cuda_bf16.h>

// Problem constants (fixed dataset: B=2048, C=9605, top-k=10)
#define NB      2048
#define NC      9605
#define TOPK    10
#define CAP     256
#define NT      256
#define THRESH  2.3f   // ~103 candidates/row expected; fallback covers <10 or >CAP

// Scratch (no allocations allowed)
__device__ float g_rowsum[NB];
__device__ int   g_topidx[NB * TOPK];
__device__ int   g_flags[NB];

__device__ __forceinline__ float rcp_fast(float a) {
    float r; asm("rcp.approx.f32 %0, %1;" : "=f"(r) : "f"(a)); return r;
}

__device__ __forceinline__ unsigned long long umax64(unsigned long long a, unsigned long long b) {
    return a > b ? a : b;
}

// base*w for one element.
// y=0: base=log(min(1-p+0.05,1)), w=(1-xs_neg)^4 = max(p-0.05,0)^4
// y=1: base=log(max(p,eps)),      w=(1-p)
__device__ __forceinline__ float term_val(float xv, float yv) {
    float t   = __expf(-xv);           // FMUL + MUFU.EX2
    float sig = rcp_fast(1.0f + t);    // FADD + MUFU.RCP
    float u   = fmaxf(sig - 0.05f, 0.0f);
    float u2  = u * u;
    bool  pos = yv > 0.5f;
    float larg = pos ? fmaxf(sig, 1e-8f) : (1.05f - sig);
    float wmul = pos ? (1.0f - sig)      : (u2 * u2);
    return __logf(larg) * wmul;        // MUFU.LG2 + FMULs
}

// ordered-uint key for full-range float (fallback path; candidates in fast path are >0)
__device__ __forceinline__ unsigned orderf(float v) {
    unsigned b = __float_as_uint(v);
    return (b & 0x80000000u) ? ~b : (b | 0x80000000u);
}

__global__ void __launch_bounds__(NT)
loss_main_kernel(const float* __restrict__ x, const float* __restrict__ y,
                 const int* __restrict__ ci, int n1,
                 const int* __restrict__ ri, int n2,
                 const int* __restrict__ di, int n3)
{
    __shared__ float              s_val[CAP];
    __shared__ int                s_idx[CAP];
    __shared__ unsigned long long s_key[CAP];
    __shared__ unsigned long long s_wkey[NT / 32];
    __shared__ float              s_wsum[NT / 32];
    __shared__ unsigned long long s_kmax;
    __shared__ int                s_cnt;
    __shared__ int                s_flags;
    __shared__ int                s_sel[TOPK];

    const int row  = blockIdx.x;
    const int tid  = threadIdx.x;
    const int lane = tid & 31;
    const int wid  = tid >> 5;

    if (tid == 0) { s_cnt = 0; s_flags = 0; }
    __syncthreads();

    const float* __restrict__ xr = x + (size_t)row * NC;
    const float* __restrict__ yr = y + (size_t)row * NC;

    // ---- main streaming pass: sum base*w, collect top-k candidates ----
    float acc = 0.0f;
    #pragma unroll 4
    for (int j = tid; j < NC; j += NT) {
        float xv = xr[j];
        float yv = yr[j];
        acc += term_val(xv, yv);
        if (xv > THRESH) {
            int p = atomicAdd(&s_cnt, 1);
            if (p < CAP) { s_val[p] = xv; s_idx[p] = j; }
        }
    }

    // ---- ground-truth whitelist flags (y at the three index lists) ----
    int ntot = n1 + n2 + n3;
    for (int t = tid; t < ntot; t += NT) {
        int cls, bit;
        if (t < n1)           { cls = ci[t];          bit = 1; }
        else if (t < n1 + n2) { cls = ri[t - n1];     bit = 2; }
        else                  { cls = di[t - n1 - n2]; bit = 4; }
        if (yr[cls] > 0.5f) atomicOr(&s_flags, bit);
    }

    // ---- row sum reduction ----
    #pragma unroll
    for (int o = 16; o > 0; o >>= 1) acc += __shfl_down_sync(0xFFFFFFFFu, acc, o);
    if (lane == 0) s_wsum[wid] = acc;
    __syncthreads();
    if (tid == 0) {
        float s = 0.0f;
        #pragma unroll
        for (int i = 0; i < NT / 32; i++) s += s_wsum[i];
        g_rowsum[row] = s;
        g_flags[row]  = s_flags;
    }

    int cntraw = s_cnt;                 // valid after the sync above
    int cnt    = min(cntraw, CAP);
    bool fast  = (cntraw >= TOPK) && (cntraw <= CAP);

    if (fast) {
        // key: [val bits | ~idx]  -> larger val wins, tie -> smaller idx wins
        unsigned long long mykey = 0ull;
        if (tid < cnt)
            mykey = ((unsigned long long)__float_as_uint(s_val[tid]) << 32)
                  | (unsigned long long)(unsigned)(~s_idx[tid]);
        s_key[tid] = mykey;
        __syncthreads();

        for (int r = 0; r < TOPK; r++) {
            unsigned long long k = s_key[tid];
            #pragma unroll
            for (int o = 16; o > 0; o >>= 1)
                k = umax64(k, __shfl_down_sync(0xFFFFFFFFu, k, o));
            if (lane == 0) s_wkey[wid] = k;
            __syncthreads();
            if (tid == 0) {
                unsigned long long m = s_wkey[0];
                #pragma unroll
                for (int i = 1; i < NT / 32; i++) m = umax64(m, s_wkey[i]);
                s_kmax = m;
                g_topidx[row * TOPK + r] = (int)(~(unsigned)m);
            }
            __syncthreads();
            if (s_key[tid] == s_kmax) s_key[tid] = 0ull;  // winner drops out (unique key)
            __syncthreads();
        }
    } else {
        // exact (never expected on this data): 10 block-argmax rounds over full row
        for (int r = 0; r < TOPK; r++) {
            unsigned long long best = 0ull;
            for (int j = tid; j < NC; j += NT) {
                bool taken = false;
                for (int q = 0; q < r; q++) if (s_sel[q] == j) taken = true;
                if (!taken) {
                    unsigned long long key =
                        ((unsigned long long)orderf(xr[j]) << 32)
                      | (unsigned long long)(unsigned)(~j);
                    best = umax64(best, key);
                }
            }
            #pragma unroll
            for (int o = 16; o > 0; o >>= 1)
                best = umax64(best, __shfl_down_sync(0xFFFFFFFFu, best, o));
            if (lane == 0) s_wkey[wid] = best;
            __syncthreads();
            if (tid == 0) {
                unsigned long long m = s_wkey[0];
                #pragma unroll
                for (int i = 1; i < NT / 32; i++) m = umax64(m, s_wkey[i]);
                int j = (int)(~(unsigned)m);
                s_sel[r] = j;
                g_topidx[row * TOPK + r] = j;
            }
            __syncthreads();
        }
    }
}

// One block: per-row whitelist multiplier logic + corrections + final reduce
__global__ void __launch_bounds__(NT)
loss_finalize_kernel(const float* __restrict__ x, const float* __restrict__ y,
                     const int* __restrict__ wl_map, float* __restrict__ out)
{
    __shared__ float s_wsum[NT / 32];
    const int tid  = threadIdx.x;
    const int lane = tid & 31;
    const int wid  = tid >> 5;

    float part = 0.0f;
    for (int row = tid; row < NB; row += NT) {
        int  flags = g_flags[row];
        bool has1  = (flags & 1) != 0;
        bool has2  = (flags & 2) != 0;
        bool has3  = (flags & 4) != 0;
        bool gt4   = !(has1 || has2 || has3);

        const float* __restrict__ xr = x + (size_t)row * NC;
        const float* __restrict__ yr = y + (size_t)row * NC;

        int   idxs[TOPK];
        float fm[TOPK];
        bool  found = false;
        #pragma unroll
        for (int r = 0; r < TOPK; r++) {
            int j = g_topidx[row * TOPK + r];
            idxs[r] = j;
            int  wl     = wl_map[j];
            bool in_map = wl > 0;
            bool in_gt  = ((wl == 1) && has1) || ((wl == 2) && has2) ||
                          ((wl == 3) && has3) || ((wl == 4) && gt4);
            float f = (in_map && gt4) ? 0.5f : 1.0f;
            if (in_map && !in_gt && !found) f *= 2.0f;
            fm[r] = f;
            found = found || (in_map && in_gt);
        }
        float extra = found ? 1.0f : 2.0f;

        float corr = 0.0f;
        #pragma unroll
        for (int r = 0; r < TOPK; r++) {
            float m = fm[r] * extra;
            if (m != 1.0f) {
                int j = idxs[r];
                corr += (m - 1.0f) * term_val(xr[j], yr[j]);
            }
        }
        part += g_rowsum[row] + corr;
    }

    #pragma unroll
    for (int o = 16; o > 0; o >>= 1) part += __shfl_down_sync(0xFFFFFFFFu, part, o);
    if (lane == 0) s_wsum[wid] = part;
    __syncthreads();
    if (tid == 0) {
        float s = 0.0f;
        #pragma unroll
        for (int i = 0; i < NT / 32; i++) s += s_wsum[i];
        out[0] = -s;
    }
}

extern "C" void kernel_launch(void* const* d_in, const int* in_sizes, int n_in,
                              void* d_out, int out_size)
{
    const float* x  = (const float*)d_in[0];
    const float* y  = (const float*)d_in[1];
    const int*   ci = (const int*)d_in[2];
    const int*   ri = (const int*)d_in[3];
    const int*   di = (const int*)d_in[4];
    const int*   wl = (const int*)d_in[5];
    int n1 = in_sizes[2], n2 = in_sizes[3], n3 = in_sizes[4];
    float* out = (float*)d_out;

    loss_main_kernel<<<NB, NT>>>(x, y, ci, n1, ri, n2, di, n3);
    loss_finalize_kernel<<<1, NT>>>(x, y, wl, out);
}

// round 3
// speedup vs baseline: 2.2120x; 2.2120x over previous
#include <cuda_runtime.h>
#include <cuda_bf16.h>

// Problem constants (fixed dataset: B=2048, C=9605, top-k=10)
#define NB      2048
#define NC      9605
#define TOPK    10
#define CAP     256
#define NT      256
#define THRESH  2.3f   // ~103 candidates/row expected; fallback covers <10 or >CAP

// Scratch (no allocations allowed)
__device__ float g_rowfinal[NB];

__device__ __forceinline__ float rcp_fast(float a) {
    float r; asm("rcp.approx.f32 %0, %1;" : "=f"(r) : "f"(a)); return r;
}

__device__ __forceinline__ unsigned long long umax64(unsigned long long a, unsigned long long b) {
    return a > b ? a : b;
}

// base*w for one element.
// y=0: base=log(min(1-p+0.05,1)), w=(1-xs_neg)^4 = max(p-0.05,0)^4
// y=1: base=log(max(p,eps)),      w=(1-p)
__device__ __forceinline__ float term_val(float xv, float yv) {
    float t   = __expf(-xv);           // FMUL + MUFU.EX2
    float sig = rcp_fast(1.0f + t);    // FADD + MUFU.RCP
    float u   = fmaxf(sig - 0.05f, 0.0f);
    float u2  = u * u;
    bool  pos = yv > 0.5f;
    float larg = pos ? fmaxf(sig, 1e-8f) : (1.05f - sig);
    float wmul = pos ? (1.0f - sig)      : (u2 * u2);
    return __logf(larg) * wmul;        // MUFU.LG2 + FMULs
}

// ordered-uint key for full-range float (fallback path)
__device__ __forceinline__ unsigned orderf(float v) {
    unsigned b = __float_as_uint(v);
    return (b & 0x80000000u) ? ~b : (b | 0x80000000u);
}

__global__ void __launch_bounds__(NT)
loss_main_kernel(const float* __restrict__ x, const float* __restrict__ y,
                 const int* __restrict__ ci, int n1,
                 const int* __restrict__ ri, int n2,
                 const int* __restrict__ di, int n3,
                 const int* __restrict__ wl_map)
{
    __shared__ float              s_val[CAP];
    __shared__ int                s_idx[CAP];
    __shared__ unsigned long long s_key[CAP];
    __shared__ unsigned long long s_wkey[NT / 32];
    __shared__ float              s_wsum[NT / 32];
    __shared__ unsigned long long s_kmax;
    __shared__ int                s_cnt;
    __shared__ int                s_flags;
    __shared__ int                s_sel[TOPK];
    __shared__ int                s_wl[TOPK];
    __shared__ float              s_term[TOPK];
    __shared__ float              s_rowsum;

    const int row  = blockIdx.x;
    const int tid  = threadIdx.x;
    const int lane = tid & 31;
    const int wid  = tid >> 5;

    if (tid == 0) { s_cnt = 0; s_flags = 0; }
    __syncthreads();

    const float* __restrict__ xr = x + (size_t)row * NC;
    const float* __restrict__ yr = y + (size_t)row * NC;

    // ---- main streaming pass: aligned float4, sum base*w, collect candidates ----
    float acc = 0.0f;

    // prologue: bring row pointer to 16B alignment (row stride = 9605 floats)
    const int prol = (4 - (row & 3)) & 3;       // 0..3 scalar elems
    if (tid < prol) {
        float xv = xr[tid];
        float yv = yr[tid];
        acc += term_val(xv, yv);
        if (xv > THRESH) {
            int p = atomicAdd(&s_cnt, 1);
            if (p < CAP) { s_val[p] = xv; s_idx[p] = tid; }
        }
    }

    const int nrem  = NC - prol;
    const int nvec  = nrem >> 2;                 // float4 count
    const float4* __restrict__ x4 = (const float4*)(xr + prol);
    const float4* __restrict__ y4 = (const float4*)(yr + prol);

    for (int v = tid; v < nvec; v += NT) {
        float4 xv = x4[v];
        float4 yv = y4[v];
        int base = prol + (v << 2);
        acc += term_val(xv.x, yv.x);
        acc += term_val(xv.y, yv.y);
        acc += term_val(xv.z, yv.z);
        acc += term_val(xv.w, yv.w);
        if (xv.x > THRESH) { int p = atomicAdd(&s_cnt, 1); if (p < CAP) { s_val[p] = xv.x; s_idx[p] = base + 0; } }
        if (xv.y > THRESH) { int p = atomicAdd(&s_cnt, 1); if (p < CAP) { s_val[p] = xv.y; s_idx[p] = base + 1; } }
        if (xv.z > THRESH) { int p = atomicAdd(&s_cnt, 1); if (p < CAP) { s_val[p] = xv.z; s_idx[p] = base + 2; } }
        if (xv.w > THRESH) { int p = atomicAdd(&s_cnt, 1); if (p < CAP) { s_val[p] = xv.w; s_idx[p] = base + 3; } }
    }

    // tail
    for (int j = prol + (nvec << 2) + tid; j < NC; j += NT) {
        float xv = xr[j];
        float yv = yr[j];
        acc += term_val(xv, yv);
        if (xv > THRESH) {
            int p = atomicAdd(&s_cnt, 1);
            if (p < CAP) { s_val[p] = xv; s_idx[p] = j; }
        }
    }

    // ---- ground-truth whitelist flags (y at the three index lists) ----
    int ntot = n1 + n2 + n3;
    for (int t = tid; t < ntot; t += NT) {
        int cls, bit;
        if (t < n1)           { cls = ci[t];           bit = 1; }
        else if (t < n1 + n2) { cls = ri[t - n1];      bit = 2; }
        else                  { cls = di[t - n1 - n2]; bit = 4; }
        if (yr[cls] > 0.5f) atomicOr(&s_flags, bit);
    }

    // ---- row sum reduction ----
    #pragma unroll
    for (int o = 16; o > 0; o >>= 1) acc += __shfl_down_sync(0xFFFFFFFFu, acc, o);
    if (lane == 0) s_wsum[wid] = acc;
    __syncthreads();
    if (tid == 0) {
        float s = 0.0f;
        #pragma unroll
        for (int i = 0; i < NT / 32; i++) s += s_wsum[i];
        s_rowsum = s;
    }

    int cntraw = s_cnt;                 // valid after the sync above
    int cnt    = min(cntraw, CAP);
    bool fast  = (cntraw >= TOPK) && (cntraw <= CAP);

    if (fast) {
        // key: [val bits | ~idx]  -> larger val wins, tie -> smaller idx wins
        unsigned long long mykey = 0ull;
        if (tid < cnt)
            mykey = ((unsigned long long)__float_as_uint(s_val[tid]) << 32)
                  | (unsigned long long)(unsigned)(~s_idx[tid]);
        s_key[tid] = mykey;
        __syncthreads();

        for (int r = 0; r < TOPK; r++) {
            unsigned long long k = s_key[tid];
            #pragma unroll
            for (int o = 16; o > 0; o >>= 1)
                k = umax64(k, __shfl_down_sync(0xFFFFFFFFu, k, o));
            if (lane == 0) s_wkey[wid] = k;
            __syncthreads();
            if (tid == 0) {
                unsigned long long m = s_wkey[0];
                #pragma unroll
                for (int i = 1; i < NT / 32; i++) m = umax64(m, s_wkey[i]);
                s_kmax = m;
                s_sel[r] = (int)(~(unsigned)m);
            }
            __syncthreads();
            if (s_key[tid] == s_kmax) s_key[tid] = 0ull;  // winner drops out (unique key)
            __syncthreads();
        }
    } else {
        // exact (never expected on this data): 10 block-argmax rounds over full row
        for (int r = 0; r < TOPK; r++) {
            unsigned long long best = 0ull;
            for (int j = tid; j < NC; j += NT) {
                bool taken = false;
                for (int q = 0; q < r; q++) if (s_sel[q] == j) taken = true;
                if (!taken) {
                    unsigned long long key =
                        ((unsigned long long)orderf(xr[j]) << 32)
                      | (unsigned long long)(unsigned)(~j);
                    best = umax64(best, key);
                }
            }
            #pragma unroll
            for (int o = 16; o > 0; o >>= 1)
                best = umax64(best, __shfl_down_sync(0xFFFFFFFFu, best, o));
            if (lane == 0) s_wkey[wid] = best;
            __syncthreads();
            if (tid == 0) {
                unsigned long long m = s_wkey[0];
                #pragma unroll
                for (int i = 1; i < NT / 32; i++) m = umax64(m, s_wkey[i]);
                s_sel[r] = (int)(~(unsigned)m);
            }
            __syncthreads();
        }
    }

    // ---- in-block finalize: wl_map gathers + recomputed terms for top-10 ----
    if (tid < TOPK) {
        int j = s_sel[tid];
        s_wl[tid]   = wl_map[j];                 // L2-resident (shared across blocks)
        s_term[tid] = term_val(xr[j], yr[j]);    // L1/L2-hot
    }
    __syncthreads();

    if (tid == 0) {
        int  flags = s_flags;
        bool has1  = (flags & 1) != 0;
        bool has2  = (flags & 2) != 0;
        bool has3  = (flags & 4) != 0;
        bool gt4   = !(has1 || has2 || has3);

        float fm[TOPK];
        bool  found = false;
        #pragma unroll
        for (int r = 0; r < TOPK; r++) {
            int  wl     = s_wl[r];
            bool in_map = wl > 0;
            bool in_gt  = ((wl == 1) && has1) || ((wl == 2) && has2) ||
                          ((wl == 3) && has3) || ((wl == 4) && gt4);
            float f = (in_map && gt4) ? 0.5f : 1.0f;
            if (in_map && !in_gt && !found) f *= 2.0f;
            fm[r] = f;
            found = found || (in_map && in_gt);
        }
        float extra = found ? 1.0f : 2.0f;

        float corr = 0.0f;
        #pragma unroll
        for (int r = 0; r < TOPK; r++) {
            float m = fm[r] * extra;
            corr += (m - 1.0f) * s_term[r];      // zero when m==1
        }
        g_rowfinal[row] = s_rowsum + corr;
    }
}

// Tiny final reduce: 2048 floats -> scalar
__global__ void __launch_bounds__(NT)
loss_reduce_kernel(float* __restrict__ out)
{
    __shared__ float s_wsum[NT / 32];
    const int tid  = threadIdx.x;
    const int lane = tid & 31;
    const int wid  = tid >> 5;

    float part = 0.0f;
    #pragma unroll
    for (int i = tid; i < NB; i += NT) part += g_rowfinal[i];

    #pragma unroll
    for (int o = 16; o > 0; o >>= 1) part += __shfl_down_sync(0xFFFFFFFFu, part, o);
    if (lane == 0) s_wsum[wid] = part;
    __syncthreads();
    if (tid == 0) {
        float s = 0.0f;
        #pragma unroll
        for (int i = 0; i < NT / 32; i++) s += s_wsum[i];
        out[0] = -s;
    }
}

extern "C" void kernel_launch(void* const* d_in, const int* in_sizes, int n_in,
                              void* d_out, int out_size)
{
    const float* x  = (const float*)d_in[0];
    const float* y  = (const float*)d_in[1];
    const int*   ci = (const int*)d_in[2];
    const int*   ri = (const int*)d_in[3];
    const int*   di = (const int*)d_in[4];
    const int*   wl = (const int*)d_in[5];
    int n1 = in_sizes[2], n2 = in_sizes[3], n3 = in_sizes[4];
    float* out = (float*)d_out;

    loss_main_kernel<<<NB, NT>>>(x, y, ci, n1, ri, n2, di, n3, wl);
    loss_reduce_kernel<<<1, NT>>>(out);
}